// round 5
// baseline (speedup 1.0000x reference)
#include <cuda_runtime.h>
#include <math.h>
#include <stdint.h>

typedef unsigned long long ull;

// ---------------- problem constants ----------------
#define T_SEQ 1024
#define HID   2880
#define NH    64
#define KVH   8
#define DH    64
#define WIN   128
#define QKV_N 5120           // NH*DH + 2*KVH*DH
#define K_OFF 4096           // NH*DH
#define V_OFF 4608           // NH*DH + KVH*DH
#define ATT_N 4096           // NH*DH

// ---------------- scratch (device globals; no allocation allowed) ----------------
__device__ float g_xn[(size_t)T_SEQ * HID];
__device__ float g_qkv[(size_t)T_SEQ * QKV_N];
__device__ float g_attn[(size_t)T_SEQ * ATT_N];
__device__ float g_cos[T_SEQ * 32];
__device__ float g_sin[T_SEQ * 32];

// ---------------- RMSNorm ----------------
__global__ void rmsnorm_kernel(const float* __restrict__ x,
                               const float* __restrict__ scale,
                               float* __restrict__ xn)
{
    const int t = blockIdx.x;
    const float4* xr = reinterpret_cast<const float4*>(x + (size_t)t * HID);
    float ss = 0.f;
    for (int i = threadIdx.x; i < HID / 4; i += 256) {
        float4 v = xr[i];
        ss += v.x * v.x + v.y * v.y + v.z * v.z + v.w * v.w;
    }
    __shared__ float red[8];
    for (int off = 16; off; off >>= 1) ss += __shfl_xor_sync(0xffffffffu, ss, off);
    if ((threadIdx.x & 31) == 0) red[threadIdx.x >> 5] = ss;
    __syncthreads();
    if (threadIdx.x < 32) {
        float v = (threadIdx.x < 8) ? red[threadIdx.x] : 0.f;
        for (int off = 4; off; off >>= 1) v += __shfl_xor_sync(0xffffffffu, v, off);
        if (threadIdx.x == 0) red[0] = v;
    }
    __syncthreads();
    const float r = rsqrtf(red[0] / (float)HID + 1e-5f);
    const float4* sr = reinterpret_cast<const float4*>(scale);
    float4* outr = reinterpret_cast<float4*>(xn + (size_t)t * HID);
    for (int i = threadIdx.x; i < HID / 4; i += 256) {
        float4 v = xr[i];
        float4 sv = sr[i];
        outr[i] = make_float4(v.x * r * sv.x, v.y * r * sv.y,
                              v.z * r * sv.z, v.w * r * sv.w);
    }
}

// ---------------- YaRN RoPE cos/sin table ----------------
__global__ void rope_table_kernel(const int* __restrict__ positions,
                                  float* __restrict__ gcos,
                                  float* __restrict__ gsin)
{
    const int t = blockIdx.x;
    const int i = threadIdx.x;  // 0..31
    const double pos = (double)positions[t];
    const double TWO_PI = 6.283185307179586476925286766559;
    const double BASE = 150000.0;
    const double freq = pow(BASE, (2.0 * i) / 64.0);
    const double conc = 0.1 * log(32.0) + 1.0;
    const double lo = 32.0 * log(4096.0 / (32.0 * TWO_PI)) / log(BASE);
    const double hi = 32.0 * log(4096.0 / (1.0 * TWO_PI)) / log(BASE);
    const double interp = 1.0 / (32.0 * freq);
    const double extrap = 1.0 / freq;
    double ramp = ((double)i - lo) / (hi - lo);
    ramp = fmin(fmax(ramp, 0.0), 1.0);
    const double mask = 1.0 - ramp;
    const double inv = interp * (1.0 - mask) + extrap * mask;
    const double ang = pos * inv;
    gcos[t * 32 + i] = (float)(cos(ang) * conc);
    gsin[t * 32 + i] = (float)(sin(ang) * conc);
}

// ---------------- apply RoPE in place to q and k (128-thread blocks) ----------------
__global__ void __launch_bounds__(128)
rope_apply_kernel(float* __restrict__ qkv,
                  const float* __restrict__ gcos,
                  const float* __restrict__ gsin)
{
    const int t = blockIdx.y;
    const int hh = blockIdx.x * 4 + (threadIdx.x >> 5);   // 0..71
    const int i = threadIdx.x & 31;
    const size_t base = (size_t)t * QKV_N +
                        (hh < NH ? (size_t)hh * DH : (size_t)K_OFF + (size_t)(hh - NH) * DH);
    const float c = gcos[t * 32 + i];
    const float s = gsin[t * 32 + i];
    const float x1 = qkv[base + i];
    const float x2 = qkv[base + 32 + i];
    qkv[base + i]      = x1 * c - x2 * s;
    qkv[base + 32 + i] = x2 * c + x1 * s;
}

// ================= packed-f32x2 SIMT GEMM =================
// C(M,N) = A(M,K)@B(K,N) + bias (+resid), all fp32.
// 128x128x16 tile, 256 threads, per-thread 8x8 via fma.rn.f32x2 (2 MACs/instr).
// A kept in smem duplicated as {a,a} 8-byte pairs with granule swizzle so the
// 8 lane-groups of a warp hit 8 distinct bank-quads (conflict-free LDS.128).

#define FMA2(d, a, b) \
    asm("fma.rn.f32x2 %0, %1, %2, %0;" : "+l"(d) : "l"(a), "l"(b))

__device__ __forceinline__ float2 unpack_f2(ull v)
{
    float2 f;
    asm("mov.b64 {%0, %1}, %2;" : "=f"(f.x), "=f"(f.y) : "l"(v));
    return f;
}

#define BKG 16
#define ASTRIDE 264   // floats per k-row of As2 (128 dup-pairs = 256 + 8 pad)

__device__ __forceinline__ int swz_gran(int g)   // granule swizzle within a k-row
{
    return g ^ ((g >> 3) & 3);
}

__global__ void __launch_bounds__(256, 2)
f32x2_gemm_kernel(int M, int N, int K,
                  const float* __restrict__ A,
                  const float* __restrict__ B,
                  const float* __restrict__ bias,
                  const float* __restrict__ resid,
                  float* __restrict__ C)
{
    __shared__ __align__(16) float As2[BKG][ASTRIDE];  // duplicated A pairs
    __shared__ __align__(16) float Bs[BKG][128];

    const int tid = threadIdx.x;
    const int lane = tid & 31;
    const int wid = tid >> 5;
    const int wm = wid >> 2;            // 0..1
    const int wn = wid & 3;             // 0..3
    const int Gr = lane >> 2;           // 0..7 row-group
    const int n0t = wn * 32 + (lane & 3) * 8;
    const int m0t = wm * 64 + Gr * 8;
    const int m0 = blockIdx.y * 128;
    const int n0 = blockIdx.x * 128;

    ull acc[8][4];
#pragma unroll
    for (int i = 0; i < 8; i++)
#pragma unroll
        for (int j = 0; j < 4; j++) acc[i][j] = 0ull;

    // fill mappings
    const int arow0 = tid >> 2, ak0 = tid & 3;            // idx = tid
    const int arow1 = (tid + 256) >> 2, ak1 = tid & 3;    // idx = tid + 256
    const int bk0 = tid >> 5, bc0 = tid & 31;             // idx = tid
    const int bk1 = (tid + 256) >> 5, bc1 = tid & 31;     // idx = tid + 256

    const int nk = K / BKG;
    float4 av0, av1, bv0, bv1;

    // ---- load chunk 0 ----
    av0 = *reinterpret_cast<const float4*>(&A[(size_t)(m0 + arow0) * K + ak0 * 4]);
    av1 = *reinterpret_cast<const float4*>(&A[(size_t)(m0 + arow1) * K + ak1 * 4]);
    {
        int c0 = n0 + bc0 * 4, c1 = n0 + bc1 * 4;
        bv0 = (c0 < N) ? *reinterpret_cast<const float4*>(&B[(size_t)bk0 * N + c0])
                       : make_float4(0.f, 0.f, 0.f, 0.f);
        bv1 = (c1 < N) ? *reinterpret_cast<const float4*>(&B[(size_t)bk1 * N + c1])
                       : make_float4(0.f, 0.f, 0.f, 0.f);
    }

#define STORE_TILES()                                                          \
    do {                                                                       \
        int gA0 = swz_gran(arow0 >> 1) * 4 + (arow0 & 1) * 2;                  \
        int gA1 = swz_gran(arow1 >> 1) * 4 + (arow1 & 1) * 2;                  \
        const float a0c[4] = {av0.x, av0.y, av0.z, av0.w};                     \
        const float a1c[4] = {av1.x, av1.y, av1.z, av1.w};                     \
        _Pragma("unroll")                                                      \
        for (int c = 0; c < 4; c++) {                                          \
            *reinterpret_cast<float2*>(&As2[ak0 * 4 + c][gA0]) =               \
                make_float2(a0c[c], a0c[c]);                                   \
            *reinterpret_cast<float2*>(&As2[ak1 * 4 + c][gA1]) =               \
                make_float2(a1c[c], a1c[c]);                                   \
        }                                                                      \
        *reinterpret_cast<float4*>(&Bs[bk0][bc0 * 4]) = bv0;                   \
        *reinterpret_cast<float4*>(&Bs[bk1][bc1 * 4]) = bv1;                   \
    } while (0)

    STORE_TILES();
    __syncthreads();

    for (int ch = 0; ch < nk; ch++) {
        if (ch + 1 < nk) {
            const int k0 = (ch + 1) * BKG;
            av0 = *reinterpret_cast<const float4*>(
                &A[(size_t)(m0 + arow0) * K + k0 + ak0 * 4]);
            av1 = *reinterpret_cast<const float4*>(
                &A[(size_t)(m0 + arow1) * K + k0 + ak1 * 4]);
            int c0 = n0 + bc0 * 4, c1 = n0 + bc1 * 4;
            bv0 = (c0 < N) ? *reinterpret_cast<const float4*>(
                                 &B[(size_t)(k0 + bk0) * N + c0])
                           : make_float4(0.f, 0.f, 0.f, 0.f);
            bv1 = (c1 < N) ? *reinterpret_cast<const float4*>(
                                 &B[(size_t)(k0 + bk1) * N + c1])
                           : make_float4(0.f, 0.f, 0.f, 0.f);
        }

        const int gb = wm * 32 + Gr * 4;  // granule base for this thread's A rows
#pragma unroll
        for (int k = 0; k < BKG; k++) {
            ulonglong2 A0 = *reinterpret_cast<const ulonglong2*>(
                &As2[k][swz_gran(gb + 0) * 4]);
            ulonglong2 A1 = *reinterpret_cast<const ulonglong2*>(
                &As2[k][swz_gran(gb + 1) * 4]);
            ulonglong2 A2 = *reinterpret_cast<const ulonglong2*>(
                &As2[k][swz_gran(gb + 2) * 4]);
            ulonglong2 A3 = *reinterpret_cast<const ulonglong2*>(
                &As2[k][swz_gran(gb + 3) * 4]);
            ulonglong2 B0 = *reinterpret_cast<const ulonglong2*>(&Bs[k][n0t]);
            ulonglong2 B1 = *reinterpret_cast<const ulonglong2*>(&Bs[k][n0t + 4]);
            ull a[8] = {A0.x, A0.y, A1.x, A1.y, A2.x, A2.y, A3.x, A3.y};
            ull b[4] = {B0.x, B0.y, B1.x, B1.y};
#pragma unroll
            for (int mm = 0; mm < 8; mm++)
#pragma unroll
                for (int pp = 0; pp < 4; pp++)
                    FMA2(acc[mm][pp], a[mm], b[pp]);
        }
        __syncthreads();
        if (ch + 1 < nk) {
            STORE_TILES();
            __syncthreads();
        }
    }

    // ---- epilogue ----
#pragma unroll
    for (int mm = 0; mm < 8; mm++) {
        const int row = m0 + m0t + mm;
#pragma unroll
        for (int pp = 0; pp < 4; pp++) {
            const int col = n0 + n0t + pp * 2;
            if (col < N) {
                float2 f = unpack_f2(acc[mm][pp]);
                f.x += bias[col];
                f.y += bias[col + 1];
                const size_t ix = (size_t)row * N + col;
                if (resid) {
                    float2 e = *reinterpret_cast<const float2*>(&resid[ix]);
                    f.x += e.x;
                    f.y += e.y;
                }
                *reinterpret_cast<float2*>(&C[ix]) = f;
            }
        }
    }
}

// ---------------- sliding-window attention with sink ----------------
// one block per (kv-head, query): all 8 GQA heads share K/V loads.
__global__ void __launch_bounds__(128)
attn_kernel(const float* __restrict__ qkv,
            const float* __restrict__ sinks,
            float* __restrict__ attn_out)
{
    const int kvh = blockIdx.x;  // 0..7
    const int t = blockIdx.y;    // 0..1023
    const int tid = threadIdx.x; // 0..127
    const int lane = tid & 31;
    const int warp = tid >> 5;

    __shared__ float qs[8][64];
    __shared__ float Vs[128][68];     // padded rows (bank spread)
    __shared__ float ps[128][8];      // transposed probs [key][head]
    __shared__ float redm[8][4];
    __shared__ float reds[8][4];
    __shared__ float outsm[8][64];

    // q for 8 heads of this group
    {
        const int g = tid >> 4, d4 = tid & 15;
        *reinterpret_cast<float4*>(&qs[g][d4 * 4]) =
            *reinterpret_cast<const float4*>(
                &qkv[(size_t)t * QKV_N + (size_t)(kvh * 8 + g) * DH + d4 * 4]);
    }

    const int jj = tid;
    const int j = t - (WIN - 1) + jj;

    // V window into smem (zero invalid rows: scratch may hold garbage/NaN)
    if (j >= 0) {
        const float* vp = &qkv[(size_t)j * QKV_N + V_OFF + (size_t)kvh * DH];
#pragma unroll
        for (int c = 0; c < 16; c++)
            *reinterpret_cast<float4*>(&Vs[jj][c * 4]) =
                *reinterpret_cast<const float4*>(&vp[c * 4]);
    } else {
#pragma unroll
        for (int c = 0; c < 16; c++)
            *reinterpret_cast<float4*>(&Vs[jj][c * 4]) =
                make_float4(0.f, 0.f, 0.f, 0.f);
    }
    __syncthreads();

    // scores: thread jj holds its K row, dots against 8 q heads
    float s[8];
    if (j >= 0) {
        float4 kr[16];
        const float* kp = &qkv[(size_t)j * QKV_N + K_OFF + (size_t)kvh * DH];
#pragma unroll
        for (int c = 0; c < 16; c++)
            kr[c] = *reinterpret_cast<const float4*>(&kp[c * 4]);
#pragma unroll
        for (int g = 0; g < 8; g++) {
            float a = 0.f;
#pragma unroll
            for (int c = 0; c < 16; c++) {
                float4 q4 = *reinterpret_cast<const float4*>(&qs[g][c * 4]);
                a += kr[c].x * q4.x + kr[c].y * q4.y +
                     kr[c].z * q4.z + kr[c].w * q4.w;
            }
            s[g] = a * 0.125f;
        }
    } else {
#pragma unroll
        for (int g = 0; g < 8; g++) s[g] = -INFINITY;
    }

    // per-head block max
#pragma unroll
    for (int g = 0; g < 8; g++) {
        float m = s[g];
        for (int off = 16; off; off >>= 1)
            m = fmaxf(m, __shfl_xor_sync(0xffffffffu, m, off));
        if (lane == 0) redm[g][warp] = m;
    }
    __syncthreads();

    float Mv[8], p[8];
#pragma unroll
    for (int g = 0; g < 8; g++) {
        const float sk = sinks[kvh * 8 + g];
        Mv[g] = fmaxf(fmaxf(fmaxf(redm[g][0], redm[g][1]),
                            fmaxf(redm[g][2], redm[g][3])), sk);
        p[g] = (j >= 0) ? expf(s[g] - Mv[g]) : 0.f;
        ps[jj][g] = p[g];
    }
#pragma unroll
    for (int g = 0; g < 8; g++) {
        float sm = p[g];
        for (int off = 16; off; off >>= 1)
            sm += __shfl_xor_sync(0xffffffffu, sm, off);
        if (lane == 0) reds[g][warp] = sm;
    }
    __syncthreads();

    float inv[8];
#pragma unroll
    for (int g = 0; g < 8; g++) {
        const float denom = reds[g][0] + reds[g][1] + reds[g][2] + reds[g][3] +
                            expf(sinks[kvh * 8 + g] - Mv[g]);
        inv[g] = 1.f / denom;
    }

    // PV: thread = (d, half); vectorized probs
    const int d = tid & 63;
    const int half = tid >> 6;
    float accv[8] = {0.f, 0.f, 0.f, 0.f, 0.f, 0.f, 0.f, 0.f};
#pragma unroll 4
    for (int k2 = half * 64; k2 < half * 64 + 64; k2++) {
        const float v = Vs[k2][d];
        float4 p0 = *reinterpret_cast<const float4*>(&ps[k2][0]);
        float4 p1 = *reinterpret_cast<const float4*>(&ps[k2][4]);
        accv[0] += p0.x * v; accv[1] += p0.y * v;
        accv[2] += p0.z * v; accv[3] += p0.w * v;
        accv[4] += p1.x * v; accv[5] += p1.y * v;
        accv[6] += p1.z * v; accv[7] += p1.w * v;
    }
    if (half == 0) {
#pragma unroll
        for (int g = 0; g < 8; g++) outsm[g][d] = accv[g];
    }
    __syncthreads();
    if (half == 1) {
#pragma unroll
        for (int g = 0; g < 8; g++) {
            const float r = (outsm[g][d] + accv[g]) * inv[g];
            attn_out[(size_t)t * ATT_N + (size_t)(kvh * 8 + g) * DH + d] = r;
        }
    }
}

// ---------------- launch ----------------
extern "C" void kernel_launch(void* const* d_in, const int* in_sizes, int n_in,
                              void* d_out, int out_size)
{
    const float* hidden     = (const float*)d_in[0];
    const int*   positions  = (const int*)d_in[1];
    const float* norm_scale = (const float*)d_in[2];
    const float* w_qkv      = (const float*)d_in[3];
    const float* b_qkv      = (const float*)d_in[4];
    const float* w_out      = (const float*)d_in[5];
    const float* b_out      = (const float*)d_in[6];
    const float* sinks      = (const float*)d_in[7];
    float* out = (float*)d_out;

    float *xn, *qkv, *attn, *gcos, *gsin;
    cudaGetSymbolAddress((void**)&xn, g_xn);
    cudaGetSymbolAddress((void**)&qkv, g_qkv);
    cudaGetSymbolAddress((void**)&attn, g_attn);
    cudaGetSymbolAddress((void**)&gcos, g_cos);
    cudaGetSymbolAddress((void**)&gsin, g_sin);

    rmsnorm_kernel<<<T_SEQ, 256>>>(hidden, norm_scale, xn);
    rope_table_kernel<<<T_SEQ, 32>>>(positions, gcos, gsin);

    // qkv = xn @ w_qkv + b_qkv   (M=1024, N=5120, K=2880)
    f32x2_gemm_kernel<<<dim3(QKV_N / 128, T_SEQ / 128), 256>>>(
        T_SEQ, QKV_N, HID, xn, w_qkv, b_qkv, nullptr, qkv);

    rope_apply_kernel<<<dim3((NH + KVH) / 4, T_SEQ), 128>>>(qkv, gcos, gsin);

    attn_kernel<<<dim3(KVH, T_SEQ), 128>>>(qkv, sinks, attn);

    // out = attn @ w_out + b_out + hidden   (M=1024, N=2880, K=4096)
    f32x2_gemm_kernel<<<dim3((HID + 127) / 128, T_SEQ / 128), 256>>>(
        T_SEQ, HID, ATT_N, attn, w_out, b_out, hidden, out);
}

// round 6
// speedup vs baseline: 6.9618x; 6.9618x over previous
#include <cuda_runtime.h>
#include <cuda_fp16.h>
#include <math.h>
#include <stdint.h>

// ---------------- problem constants ----------------
#define T_SEQ 1024
#define HID   2880
#define NH    64
#define KVH   8
#define DH    64
#define WIN   128
#define QKV_N 5120           // NH*DH + 2*KVH*DH
#define K_OFF 4096           // NH*DH
#define V_OFF 4608           // NH*DH + KVH*DH
#define ATT_N 4096           // NH*DH

#define KC1 180              // HID/16
#define KC2 256              // ATT_N/16
#define NBLK1 40             // QKV_N/128
#define NBLK2 23             // ceil(HID/128)

// ---------------- scratch (device globals; no allocation allowed) ----------------
__device__ float    g_qkv[(size_t)T_SEQ * QKV_N];
__device__ float    g_attn[(size_t)T_SEQ * ATT_N];
__device__ float    g_cos[T_SEQ * 32];
__device__ float    g_sin[T_SEQ * 32];
__device__ unsigned g_Ap1[(size_t)8 * KC1 * 1024];       // 1.47M u32
__device__ unsigned g_Ap2[(size_t)8 * KC2 * 1024];       // 2.10M u32
__device__ unsigned g_Bp1[(size_t)NBLK1 * KC1 * 1024];   // 7.37M u32
__device__ unsigned g_Bp2[(size_t)NBLK2 * KC2 * 1024];   // 6.03M u32

// ================= fragment-permuted fp16 layouts =================
// A element (row, k):  mblk=row/128, mt=(row/16)%8, r16=row%16, kc=k/16, kin=k%16
//   lane = (r16%8)*4 + (kin%8)/2 ; reg j = (r16/8) + 2*(kin/8) ; half = kin%2
//   Ap[(((mblk*KC+kc)*8+mt)*32+lane)*4+j]
// B element (k, n):    nblk=n/128, nt=(n/8)%16, kc=k/16, kin=k%16
//   lane = (n%8)*4 + (kin%8)/2 ; reg j = kin/8 ; half = kin%2
//   Bp[(((nblk*KC+kc)*16+nt)*32+lane)*2+j]

// ---------------- weight conversion (fp32 [K][N] -> permuted fp16) ----------------
__global__ void __launch_bounds__(256)
convB_kernel(const float* __restrict__ W, unsigned* __restrict__ Bp,
             int K, int N, int KC)
{
    const int t = blockIdx.x * 256 + threadIdx.x;   // one b32 dest per thread
    const int j = t & 1;
    const int l = (t >> 1) & 31;
    const int nt = (t >> 6) & 15;
    const int rest = t >> 10;
    const int kc = rest % KC;
    const int nblk = rest / KC;
    const int n = nblk * 128 + nt * 8 + (l >> 2);
    const int k0 = kc * 16 + ((l & 3) << 1) + (j << 3);
    float v0 = 0.f, v1 = 0.f;
    if (n < N) {
        v0 = W[(size_t)k0 * N + n];
        v1 = W[(size_t)(k0 + 1) * N + n];
    }
    __half2 h = __floats2half2_rn(v0, v1);
    Bp[t] = *reinterpret_cast<unsigned*>(&h);
}

// ---------------- activation conversion (fp32 [1024][K] -> permuted fp16) ----------------
__global__ void __launch_bounds__(256)
convA_kernel(const float* __restrict__ A, unsigned* __restrict__ Ap, int K, int KC)
{
    const int t = blockIdx.x;   // row
    const int mblk = t >> 7, mt = (t >> 4) & 7;
    const int lbase = (t & 7) * 4, jbase = (t >> 3) & 1;
    const float2* src = reinterpret_cast<const float2*>(A + (size_t)t * K);
    for (int idx = threadIdx.x; idx < K / 2; idx += 256) {
        const int k = idx * 2, kc = k >> 4, kin = k & 15;
        const int l = lbase + ((kin & 7) >> 1);
        const int j = jbase + ((kin >> 3) << 1);
        float2 v = src[idx];
        __half2 h = __floats2half2_rn(v.x, v.y);
        Ap[(((size_t)(mblk * KC + kc) * 8 + mt) * 32 + l) * 4 + j] =
            *reinterpret_cast<unsigned*>(&h);
    }
}

// ---------------- RMSNorm fused with convA (emits permuted fp16 A for gemm1) ----------------
__global__ void __launch_bounds__(256)
rmsnorm_convA_kernel(const float* __restrict__ x,
                     const float* __restrict__ scale,
                     unsigned* __restrict__ Ap)
{
    const int t = blockIdx.x;
    const float4* xr = reinterpret_cast<const float4*>(x + (size_t)t * HID);
    float ss = 0.f;
    for (int i = threadIdx.x; i < HID / 4; i += 256) {
        float4 v = xr[i];
        ss += v.x * v.x + v.y * v.y + v.z * v.z + v.w * v.w;
    }
    __shared__ float red[8];
    for (int off = 16; off; off >>= 1) ss += __shfl_xor_sync(0xffffffffu, ss, off);
    if ((threadIdx.x & 31) == 0) red[threadIdx.x >> 5] = ss;
    __syncthreads();
    if (threadIdx.x < 32) {
        float v = (threadIdx.x < 8) ? red[threadIdx.x] : 0.f;
        for (int off = 4; off; off >>= 1) v += __shfl_xor_sync(0xffffffffu, v, off);
        if (threadIdx.x == 0) red[0] = v;
    }
    __syncthreads();
    const float r = rsqrtf(red[0] / (float)HID + 1e-5f);

    const int mblk = t >> 7, mt = (t >> 4) & 7;
    const int lbase = (t & 7) * 4, jbase = (t >> 3) & 1;
    const float2* x2 = reinterpret_cast<const float2*>(x + (size_t)t * HID);
    const float2* s2 = reinterpret_cast<const float2*>(scale);
    for (int idx = threadIdx.x; idx < HID / 2; idx += 256) {
        const int k = idx * 2, kc = k >> 4, kin = k & 15;
        const int l = lbase + ((kin & 7) >> 1);
        const int j = jbase + ((kin >> 3) << 1);
        float2 v = x2[idx], sc = s2[idx];
        __half2 h = __floats2half2_rn(v.x * r * sc.x, v.y * r * sc.y);
        Ap[(((size_t)(mblk * KC1 + kc) * 8 + mt) * 32 + l) * 4 + j] =
            *reinterpret_cast<unsigned*>(&h);
    }
}

// ---------------- YaRN RoPE cos/sin table ----------------
__global__ void rope_table_kernel(const int* __restrict__ positions,
                                  float* __restrict__ gcos,
                                  float* __restrict__ gsin)
{
    const int t = blockIdx.x;
    const int i = threadIdx.x;  // 0..31
    const double pos = (double)positions[t];
    const double TWO_PI = 6.283185307179586476925286766559;
    const double BASE = 150000.0;
    const double freq = pow(BASE, (2.0 * i) / 64.0);
    const double conc = 0.1 * log(32.0) + 1.0;
    const double lo = 32.0 * log(4096.0 / (32.0 * TWO_PI)) / log(BASE);
    const double hi = 32.0 * log(4096.0 / (1.0 * TWO_PI)) / log(BASE);
    const double interp = 1.0 / (32.0 * freq);
    const double extrap = 1.0 / freq;
    double ramp = ((double)i - lo) / (hi - lo);
    ramp = fmin(fmax(ramp, 0.0), 1.0);
    const double mask = 1.0 - ramp;
    const double inv = interp * (1.0 - mask) + extrap * mask;
    const double ang = pos * inv;
    gcos[t * 32 + i] = (float)(cos(ang) * conc);
    gsin[t * 32 + i] = (float)(sin(ang) * conc);
}

// ---------------- apply RoPE in place to q and k ----------------
__global__ void __launch_bounds__(128)
rope_apply_kernel(float* __restrict__ qkv,
                  const float* __restrict__ gcos,
                  const float* __restrict__ gsin)
{
    const int t = blockIdx.y;
    const int hh = blockIdx.x * 4 + (threadIdx.x >> 5);   // 0..71
    const int i = threadIdx.x & 31;
    const size_t base = (size_t)t * QKV_N +
                        (hh < NH ? (size_t)hh * DH : (size_t)K_OFF + (size_t)(hh - NH) * DH);
    const float c = gcos[t * 32 + i];
    const float s = gsin[t * 32 + i];
    const float x1 = qkv[base + i];
    const float x2 = qkv[base + 32 + i];
    qkv[base + i]      = x1 * c - x2 * s;
    qkv[base + 32 + i] = x2 * c + x1 * s;
}

// ================= fp16 mma.sync GEMM (pre-permuted operands) =================
// C(M,N) = fp16(A)@fp16(B) + bias (+resid), fp32 accum.
// Block 128x128, BK=32, 256 thr (8 warps 2x4), warp tile 64x32, m16n8k16.

__device__ __forceinline__ void cp16(uint32_t dst, const void* src)
{
    asm volatile("cp.async.cg.shared.global [%0], [%1], 16;"
                 :: "r"(dst), "l"(src) : "memory");
}

#define CP_COMMIT() asm volatile("cp.async.commit_group;" ::: "memory")
#define CP_WAIT1()  asm volatile("cp.async.wait_group 1;" ::: "memory")
#define CP_WAIT0()  asm volatile("cp.async.wait_group 0;" ::: "memory")

#define MMA_F16(d, a, b) \
    asm volatile("mma.sync.aligned.m16n8k16.row.col.f32.f16.f16.f32 " \
                 "{%0,%1,%2,%3},{%4,%5,%6,%7},{%8,%9},{%0,%1,%2,%3};" \
                 : "+f"((d)[0]), "+f"((d)[1]), "+f"((d)[2]), "+f"((d)[3]) \
                 : "r"((a).x), "r"((a).y), "r"((a).z), "r"((a).w), \
                   "r"((b).x), "r"((b).y))

__global__ void __launch_bounds__(256)
hgemm_kernel(int M, int N, int K,
             const unsigned* __restrict__ Ap,
             const unsigned* __restrict__ Bp,
             const float* __restrict__ bias,
             const float* __restrict__ resid,
             float* __restrict__ C)
{
    __shared__ __align__(16) unsigned As[2][2048];
    __shared__ __align__(16) unsigned Bs[2][2048];

    const int KC = K >> 4;
    const int tid = threadIdx.x, lane = tid & 31, wid = tid >> 5;
    const int wm = wid >> 2, wn = wid & 3;
    const int mblk = blockIdx.y, nblk = blockIdx.x;
    const unsigned* Abase = Ap + (size_t)mblk * KC * 1024;
    const unsigned* Bbase = Bp + (size_t)nblk * KC * 1024;

    float acc[4][4][4];
#pragma unroll
    for (int i = 0; i < 4; i++)
#pragma unroll
        for (int j = 0; j < 4; j++)
#pragma unroll
            for (int q = 0; q < 4; q++) acc[i][j][q] = 0.f;

    const uint32_t saA = (uint32_t)__cvta_generic_to_shared(&As[0][0]);
    const uint32_t saB = (uint32_t)__cvta_generic_to_shared(&Bs[0][0]);
    const int nch = K / 32;

#define ISSUE_COPY(ch, s)                                                     \
    do {                                                                      \
        const unsigned* asrc = Abase + (size_t)(ch) * 2048;                   \
        const unsigned* bsrc = Bbase + (size_t)(ch) * 2048;                   \
        uint32_t da = saA + (s) * 8192;                                       \
        uint32_t db = saB + (s) * 8192;                                       \
        cp16(da + tid * 16, asrc + tid * 4);                                  \
        cp16(da + (tid + 256) * 16, asrc + (tid + 256) * 4);                  \
        cp16(db + tid * 16, bsrc + tid * 4);                                  \
        cp16(db + (tid + 256) * 16, bsrc + (tid + 256) * 4);                  \
        CP_COMMIT();                                                          \
    } while (0)

    ISSUE_COPY(0, 0);

    for (int ch = 0; ch < nch; ch++) {
        if (ch + 1 < nch) {
            ISSUE_COPY(ch + 1, (ch + 1) & 1);
            CP_WAIT1();
        } else {
            CP_WAIT0();
        }
        __syncthreads();

        const int s = ch & 1;
#pragma unroll
        for (int ks = 0; ks < 2; ks++) {
            uint4 af[4];
            uint2 bf[4];
            const unsigned* ab = &As[s][ks * 1024 + wm * 512 + lane * 4];
            const unsigned* bb = &Bs[s][ks * 1024 + wn * 256 + lane * 2];
#pragma unroll
            for (int mt = 0; mt < 4; mt++)
                af[mt] = *reinterpret_cast<const uint4*>(ab + mt * 128);
#pragma unroll
            for (int nt = 0; nt < 4; nt++)
                bf[nt] = *reinterpret_cast<const uint2*>(bb + nt * 64);
#pragma unroll
            for (int mt = 0; mt < 4; mt++)
#pragma unroll
                for (int nt = 0; nt < 4; nt++)
                    MMA_F16(acc[mt][nt], af[mt], bf[nt]);
        }
        __syncthreads();
    }

    // ---- epilogue ----
    const int m0 = mblk * 128 + wm * 64;
    const int n0 = nblk * 128 + wn * 32;
#pragma unroll
    for (int mt = 0; mt < 4; mt++) {
        const int r = m0 + mt * 16 + (lane >> 2);
#pragma unroll
        for (int nt = 0; nt < 4; nt++) {
            const int c = n0 + nt * 8 + ((lane & 3) << 1);
            if (c < N) {
                const float2 b = *reinterpret_cast<const float2*>(&bias[c]);
                float2 o0 = make_float2(acc[mt][nt][0] + b.x, acc[mt][nt][1] + b.y);
                float2 o1 = make_float2(acc[mt][nt][2] + b.x, acc[mt][nt][3] + b.y);
                const size_t i0 = (size_t)r * N + c;
                const size_t i1 = i0 + (size_t)8 * N;
                if (resid) {
                    float2 e0 = *reinterpret_cast<const float2*>(&resid[i0]);
                    float2 e1 = *reinterpret_cast<const float2*>(&resid[i1]);
                    o0.x += e0.x; o0.y += e0.y;
                    o1.x += e1.x; o1.y += e1.y;
                }
                *reinterpret_cast<float2*>(&C[i0]) = o0;
                *reinterpret_cast<float2*>(&C[i1]) = o1;
            }
        }
    }
}

// ---------------- sliding-window attention with sink ----------------
// one block per (kv-head, query): all 8 GQA heads share K/V loads.
__global__ void __launch_bounds__(128)
attn_kernel(const float* __restrict__ qkv,
            const float* __restrict__ sinks,
            float* __restrict__ attn_out)
{
    const int kvh = blockIdx.x;  // 0..7
    const int t = blockIdx.y;    // 0..1023
    const int tid = threadIdx.x; // 0..127
    const int lane = tid & 31;
    const int warp = tid >> 5;

    __shared__ float qs[8][64];
    __shared__ float Vs[128][68];
    __shared__ float ps[128][8];
    __shared__ float redm[8][4];
    __shared__ float reds[8][4];
    __shared__ float outsm[8][64];

    {
        const int g = tid >> 4, d4 = tid & 15;
        *reinterpret_cast<float4*>(&qs[g][d4 * 4]) =
            *reinterpret_cast<const float4*>(
                &qkv[(size_t)t * QKV_N + (size_t)(kvh * 8 + g) * DH + d4 * 4]);
    }

    const int jj = tid;
    const int j = t - (WIN - 1) + jj;

    if (j >= 0) {
        const float* vp = &qkv[(size_t)j * QKV_N + V_OFF + (size_t)kvh * DH];
#pragma unroll
        for (int c = 0; c < 16; c++)
            *reinterpret_cast<float4*>(&Vs[jj][c * 4]) =
                *reinterpret_cast<const float4*>(&vp[c * 4]);
    } else {
#pragma unroll
        for (int c = 0; c < 16; c++)
            *reinterpret_cast<float4*>(&Vs[jj][c * 4]) =
                make_float4(0.f, 0.f, 0.f, 0.f);
    }
    __syncthreads();

    float s[8];
    if (j >= 0) {
        float4 kr[16];
        const float* kp = &qkv[(size_t)j * QKV_N + K_OFF + (size_t)kvh * DH];
#pragma unroll
        for (int c = 0; c < 16; c++)
            kr[c] = *reinterpret_cast<const float4*>(&kp[c * 4]);
#pragma unroll
        for (int g = 0; g < 8; g++) {
            float a = 0.f;
#pragma unroll
            for (int c = 0; c < 16; c++) {
                float4 q4 = *reinterpret_cast<const float4*>(&qs[g][c * 4]);
                a += kr[c].x * q4.x + kr[c].y * q4.y +
                     kr[c].z * q4.z + kr[c].w * q4.w;
            }
            s[g] = a * 0.125f;
        }
    } else {
#pragma unroll
        for (int g = 0; g < 8; g++) s[g] = -INFINITY;
    }

#pragma unroll
    for (int g = 0; g < 8; g++) {
        float m = s[g];
        for (int off = 16; off; off >>= 1)
            m = fmaxf(m, __shfl_xor_sync(0xffffffffu, m, off));
        if (lane == 0) redm[g][warp] = m;
    }
    __syncthreads();

    float Mv[8], p[8];
#pragma unroll
    for (int g = 0; g < 8; g++) {
        const float sk = sinks[kvh * 8 + g];
        Mv[g] = fmaxf(fmaxf(fmaxf(redm[g][0], redm[g][1]),
                            fmaxf(redm[g][2], redm[g][3])), sk);
        p[g] = (j >= 0) ? expf(s[g] - Mv[g]) : 0.f;
        ps[jj][g] = p[g];
    }
#pragma unroll
    for (int g = 0; g < 8; g++) {
        float sm = p[g];
        for (int off = 16; off; off >>= 1)
            sm += __shfl_xor_sync(0xffffffffu, sm, off);
        if (lane == 0) reds[g][warp] = sm;
    }
    __syncthreads();

    float inv[8];
#pragma unroll
    for (int g = 0; g < 8; g++) {
        const float denom = reds[g][0] + reds[g][1] + reds[g][2] + reds[g][3] +
                            expf(sinks[kvh * 8 + g] - Mv[g]);
        inv[g] = 1.f / denom;
    }

    const int d = tid & 63;
    const int half = tid >> 6;
    float accv[8] = {0.f, 0.f, 0.f, 0.f, 0.f, 0.f, 0.f, 0.f};
#pragma unroll 4
    for (int k2 = half * 64; k2 < half * 64 + 64; k2++) {
        const float v = Vs[k2][d];
        float4 p0 = *reinterpret_cast<const float4*>(&ps[k2][0]);
        float4 p1 = *reinterpret_cast<const float4*>(&ps[k2][4]);
        accv[0] += p0.x * v; accv[1] += p0.y * v;
        accv[2] += p0.z * v; accv[3] += p0.w * v;
        accv[4] += p1.x * v; accv[5] += p1.y * v;
        accv[6] += p1.z * v; accv[7] += p1.w * v;
    }
    if (half == 0) {
#pragma unroll
        for (int g = 0; g < 8; g++) outsm[g][d] = accv[g];
    }
    __syncthreads();
    if (half == 1) {
#pragma unroll
        for (int g = 0; g < 8; g++) {
            const float r = (outsm[g][d] + accv[g]) * inv[g];
            attn_out[(size_t)t * ATT_N + (size_t)(kvh * 8 + g) * DH + d] = r;
        }
    }
}

// ---------------- launch ----------------
extern "C" void kernel_launch(void* const* d_in, const int* in_sizes, int n_in,
                              void* d_out, int out_size)
{
    const float* hidden     = (const float*)d_in[0];
    const int*   positions  = (const int*)d_in[1];
    const float* norm_scale = (const float*)d_in[2];
    const float* w_qkv      = (const float*)d_in[3];
    const float* b_qkv      = (const float*)d_in[4];
    const float* w_out      = (const float*)d_in[5];
    const float* b_out      = (const float*)d_in[6];
    const float* sinks      = (const float*)d_in[7];
    float* out = (float*)d_out;

    float *qkv, *attn, *gcos, *gsin;
    unsigned *Ap1, *Ap2, *Bp1, *Bp2;
    cudaGetSymbolAddress((void**)&qkv, g_qkv);
    cudaGetSymbolAddress((void**)&attn, g_attn);
    cudaGetSymbolAddress((void**)&gcos, g_cos);
    cudaGetSymbolAddress((void**)&gsin, g_sin);
    cudaGetSymbolAddress((void**)&Ap1, g_Ap1);
    cudaGetSymbolAddress((void**)&Ap2, g_Ap2);
    cudaGetSymbolAddress((void**)&Bp1, g_Bp1);
    cudaGetSymbolAddress((void**)&Bp2, g_Bp2);

    // 1: rope table
    rope_table_kernel<<<T_SEQ, 32>>>(positions, gcos, gsin);
    // 2: convert w_qkv -> permuted fp16
    convB_kernel<<<NBLK1 * KC1 * 4, 256>>>(w_qkv, Bp1, HID, QKV_N, KC1);
    // 3: rmsnorm + convert A1
    rmsnorm_convA_kernel<<<T_SEQ, 256>>>(hidden, norm_scale, Ap1);
    // 4 (profiled slot): qkv = xn @ w_qkv + b_qkv   (M=1024, N=5120, K=2880)
    hgemm_kernel<<<dim3(NBLK1, T_SEQ / 128), 256>>>(
        T_SEQ, QKV_N, HID, Ap1, Bp1, b_qkv, nullptr, qkv);
    // 5: rope
    rope_apply_kernel<<<dim3((NH + KVH) / 4, T_SEQ), 128>>>(qkv, gcos, gsin);
    // 6: attention
    attn_kernel<<<dim3(KVH, T_SEQ), 128>>>(qkv, sinks, attn);
    // 7: convert attention output
    convA_kernel<<<T_SEQ, 256>>>(attn, Ap2, ATT_N, KC2);
    // 8: convert w_out
    convB_kernel<<<NBLK2 * KC2 * 4, 256>>>(w_out, Bp2, ATT_N, HID, KC2);
    // 9: out = attn @ w_out + b_out + hidden   (M=1024, N=2880, K=4096)
    hgemm_kernel<<<dim3(NBLK2, T_SEQ / 128), 256>>>(
        T_SEQ, HID, ATT_N, Ap2, Bp2, b_out, hidden, out);
}